// round 15
// baseline (speedup 1.0000x reference)
#include <cuda_runtime.h>
#include <cuda_fp16.h>
#include <math.h>

// MoE router via mma.sync m16n8k16 fp16 2-plane split (3 f32-acc products):
//   logits = x[T,4096] @ W[64,4096]^T; x = xh+xm (exact residual),
//   W*64 = Wh+Wm (exact scale, undone at softmax).
// R15: KSPL=1, TM=64 -> full-K per CTA, fused in-CTA top2 epilogue (no
// partial round-trip, no top2 launch). cp.async stages x (raw fp32) and
// presplit W planes; KC=64 macro-chunks as two stride-160 sub-buffers.

#define HID  4096
#define NE   64
#define TM   64
#define KCM  64                   // macro chunk (two 32-wide sub-buffers)
#define NCH  (HID / KCM)          // 64
#define NT   256
#define XSTR 40                   // x sub-buffer row stride (floats)
#define ROWB 160                  // row stride bytes (both x and W subs)
#define SUBB (TM * ROWB)          // 10240 per sub-buffer (64 rows)
#define XSTGB (2 * SUBB)          // 20480 per x stage
#define WOFF  (2 * XSTGB)         // 40960: W buffers after 2 x stages
#define WSUB  (NE * ROWB)         // 10240 per W sub
#define WBUFB (2 * WSUB)          // 20480 per W stage
#define SMEM_BYTES (WOFF + 2 * WBUFB)    // 81920

static __device__ unsigned g_wp[NE * HID];   // presplit W planes [h2|m2] 1MB

__device__ __forceinline__ unsigned smem_u32(const void* p) {
    unsigned r;
    asm("{ .reg .u64 t; cvta.to.shared.u64 t, %1; cvt.u32.u64 %0, t; }"
        : "=r"(r) : "l"(p));
    return r;
}
__device__ __forceinline__ void pairsplit(const float* p, unsigned& h, unsigned& m) {
    float2 v = *(const float2*)p;
    __half2 hh = __float22half2_rn(v);
    float2 hb = __half22float2(hh);
    __half2 mm = __float22half2_rn(make_float2(v.x - hb.x, v.y - hb.y));
    h = *(unsigned*)&hh;
    m = *(unsigned*)&mm;
}
__device__ __forceinline__ void mma_f16(float* c, const unsigned* a, const unsigned* b) {
    asm volatile(
        "mma.sync.aligned.m16n8k16.row.col.f32.f16.f16.f32 "
        "{%0,%1,%2,%3},{%4,%5,%6,%7},{%8,%9},{%0,%1,%2,%3};"
        : "+f"(c[0]), "+f"(c[1]), "+f"(c[2]), "+f"(c[3])
        : "r"(a[0]), "r"(a[1]), "r"(a[2]), "r"(a[3]), "r"(b[0]), "r"(b[1]));
}
#define CP16(dst, src) asm volatile("cp.async.cg.shared.global [%0],[%1],16;" :: "r"(dst), "l"(src))
#define CPCOMMIT()     asm volatile("cp.async.commit_group;")
#define CPWAIT1()      asm volatile("cp.async.wait_group 1;")

// ---------------- kernel 1: W -> interleaved fp16 planes (x64 scale) --------
__global__ __launch_bounds__(256) void wsplit_kernel(const float* __restrict__ w) {
    int idx = blockIdx.x * 256 + threadIdx.x;          // float4 index (2 pairs)
    float4 v = ((const float4*)w)[idx];
    v.x *= 64.f; v.y *= 64.f; v.z *= 64.f; v.w *= 64.f;
    __half2 h0 = __float22half2_rn(make_float2(v.x, v.y));
    __half2 h1 = __float22half2_rn(make_float2(v.z, v.w));
    float2 b0 = __half22float2(h0);
    float2 b1 = __half22float2(h1);
    __half2 m0 = __float22half2_rn(make_float2(v.x - b0.x, v.y - b0.y));
    __half2 m1 = __float22half2_rn(make_float2(v.z - b1.x, v.w - b1.y));
    uint4 o;
    o.x = *(unsigned*)&h0; o.y = *(unsigned*)&m0;
    o.z = *(unsigned*)&h1; o.w = *(unsigned*)&m1;
    ((uint4*)g_wp)[idx] = o;
}

// ------ kernel 2: full-K GEMM (TM=64) + fused in-CTA top-2 epilogue --------
__global__ __launch_bounds__(NT) void moe_gemm_kernel(
    const float* __restrict__ x, float* __restrict__ out, int T, int write_map)
{
    extern __shared__ char smc[];
    const unsigned sbase = smem_u32(smc);
    const int tid = threadIdx.x;
    const int wid = tid >> 5;
    const int lane = tid & 31;
    const int tok0 = blockIdx.x * TM;

    // x cp.async: 4 x 16B/thread per macro chunk (2 subs x 2 iters)
    const float* xsrc[4]; unsigned xdst[4];
    #pragma unroll
    for (int it = 0; it < 4; it++) {
        int sub = it >> 1, itl = it & 1;
        int u = itl * NT + tid, row = u >> 3, c4 = u & 7;
        xsrc[it] = x + (size_t)(tok0 + row) * HID + sub * 32 + c4 * 4;
        xdst[it] = sbase + (unsigned)(sub * SUBB) + (unsigned)(row * ROWB + c4 * 16);
    }
    // W planes cp.async: 4 x 16B/thread per macro chunk
    const char* wsrc[4]; unsigned wdst[4];
    #pragma unroll
    for (int q = 0; q < 4; q++) {
        int sub = q >> 1, ql = q & 1;
        int u = ql * NT + tid, row = u >> 3, j = u & 7;
        wsrc[q] = (const char*)g_wp + (size_t)row * 2048 * 8 + sub * 128 + j * 16;
        wdst[q] = sbase + WOFF + (unsigned)(sub * WSUB) + (unsigned)(row * ROWB + j * 16);
    }

    float acc[4][4];
    #pragma unroll
    for (int nt = 0; nt < 4; nt++)
        #pragma unroll
        for (int i = 0; i < 4; i++) acc[nt][i] = 0.f;

    // prologue: macro chunk 0 -> stage 0
    #pragma unroll
    for (int it = 0; it < 4; it++) CP16(xdst[it], xsrc[it]);
    #pragma unroll
    for (int q = 0; q < 4; q++)  CP16(wdst[q], wsrc[q]);
    CPCOMMIT();

    const int eq = lane >> 2;               // groupID 0..7
    const int kq = lane & 3;                // threadInGroup 0..3
    const int rbase = (wid >> 1) * 16 + eq; // M rows (4 tiles of 16)
    const int ebase = (wid & 1) * 32;       // N half

    #pragma unroll 1
    for (int c = 0; c < NCH; c++) {
        __syncthreads();                    // compute c-1 done: stage (c+1)&1 free
        if (c + 1 < NCH) {
            unsigned xo = (unsigned)(((c + 1) & 1) * XSTGB);
            unsigned wo = (unsigned)(((c + 1) & 1) * WBUFB);
            #pragma unroll
            for (int it = 0; it < 4; it++) CP16(xdst[it] + xo, xsrc[it] + (c + 1) * KCM);
            #pragma unroll
            for (int q = 0; q < 4; q++)  CP16(wdst[q] + wo, wsrc[q] + (c + 1) * (KCM * 4));
        }
        CPCOMMIT();
        CPWAIT1();                          // macro chunk c landed (this thread)
        __syncthreads();                    // visible to all

        const char* stg = smc + (c & 1) * XSTGB;
        const char* wbb = smc + WOFF + (c & 1) * WBUFB;

        #pragma unroll
        for (int s = 0; s < 4; s++) {       // four k16 steps per macro chunk
            const int s2 = s >> 1, sl = s & 1;
            const int kl = sl * 16 + kq * 2;
            const float* sx = (const float*)(stg + s2 * SUBB);
            const uint2* bw = (const uint2*)(wbb + s2 * WSUB);
            unsigned Ah[4], Am[4];
            pairsplit(sx + rbase * XSTR + kl,           Ah[0], Am[0]);
            pairsplit(sx + (rbase + 8) * XSTR + kl,     Ah[1], Am[1]);
            pairsplit(sx + rbase * XSTR + kl + 8,       Ah[2], Am[2]);
            pairsplit(sx + (rbase + 8) * XSTR + kl + 8, Ah[3], Am[3]);
            unsigned Bh[4][2], Bm[4][2];
            #pragma unroll
            for (int nt = 0; nt < 4; nt++) {
                int e = ebase + nt * 8 + eq;
                uint2 t0 = bw[e * 20 + sl * 8 + kq];
                uint2 t1 = bw[e * 20 + sl * 8 + 4 + kq];
                Bh[nt][0] = t0.x; Bm[nt][0] = t0.y;
                Bh[nt][1] = t1.x; Bm[nt][1] = t1.y;
            }
            #pragma unroll
            for (int nt = 0; nt < 4; nt++) {
                mma_f16(acc[nt], Ah, Bh[nt]);
                mma_f16(acc[nt], Ah, Bm[nt]);
                mma_f16(acc[nt], Am, Bh[nt]);
            }
        }
    }

    // ---- fused epilogue: logits tile (64x64) -> smem, top-2 per token ----
    __syncthreads();                        // staging buffers now reusable
    float* lg = (float*)smc;                // 64 x 66 floats = 16896 B
    #pragma unroll
    for (int nt = 0; nt < 4; nt++) {
        int col = ebase + nt * 8 + kq * 2;
        *(float2*)(lg + rbase * 66 + col)       = make_float2(acc[nt][0], acc[nt][1]);
        *(float2*)(lg + (rbase + 8) * 66 + col) = make_float2(acc[nt][2], acc[nt][3]);
    }
    __syncthreads();

    // warp w handles tokens tok0 + w*8 .. +7
    const int c0 = lane * 2, c1 = lane * 2 + 1;
    #pragma unroll 1
    for (int j = 0; j < 8; j++) {
        int tl = wid * 8 + j;
        float2 s = *(const float2*)(lg + tl * 66 + c0);
        float v1, v2; int i1, i2;
        if (s.y > s.x) { v1 = s.y; i1 = c1; v2 = s.x; i2 = c0; }
        else           { v1 = s.x; i1 = c0; v2 = s.y; i2 = c1; }
        #pragma unroll
        for (int sh = 16; sh >= 1; sh >>= 1) {
            float ov1 = __shfl_xor_sync(0xffffffffu, v1, sh);
            int   oi1 = __shfl_xor_sync(0xffffffffu, i1, sh);
            float ov2 = __shfl_xor_sync(0xffffffffu, v2, sh);
            int   oi2 = __shfl_xor_sync(0xffffffffu, i2, sh);
            bool ob = (ov1 > v1) || (ov1 == v1 && oi1 < i1);   // jax tie-break
            float nv1 = ob ? ov1 : v1;  int ni1 = ob ? oi1 : i1;
            float cv  = ob ? v1  : ov1; int ci  = ob ? i1  : oi1;
            float sv  = ob ? ov2 : v2;  int si  = ob ? oi2 : i2;
            bool b2 = (cv > sv) || (cv == sv && ci < si);
            v2 = b2 ? cv : sv; i2 = b2 ? ci : si;
            v1 = nv1; i1 = ni1;
        }
        // logits carry the exact x64 W scale; undo on the difference (exact)
        float ex = expf((v2 - v1) * 0.015625f);   // <= 1, stable
        float inv = 1.f / (1.f + ex);
        float pp1 = inv, pp2 = ex * inv;

        int t = tok0 + tl;
        float2 po;
        po.x = (c0 == i1) ? pp1 : ((c0 == i2) ? pp2 : 0.f);
        po.y = (c1 == i1) ? pp1 : ((c1 == i2) ? pp2 : 0.f);
        *(float2*)(out + (size_t)t * NE + c0) = po;
        if (write_map) {
            float2 mo;
            mo.x = (c0 == i1 || c0 == i2) ? 1.f : 0.f;
            mo.y = (c1 == i1 || c1 == i2) ? 1.f : 0.f;
            *(float2*)(out + (size_t)T * NE + (size_t)t * NE + c0) = mo;
        }
    }
}

extern "C" void kernel_launch(void* const* d_in, const int* in_sizes, int n_in,
                              void* d_out, int out_size) {
    const float* x = (const float*)d_in[0];   // [2048,4,4096] fp32
    const float* w = (const float*)d_in[1];   // [64,4096] fp32
    float* out = (float*)d_out;
    int T = in_sizes[0] / HID;                // 8192
    int write_map = (out_size >= 2 * T * NE) ? 1 : 0;

    static int smem_set = 0;
    if (!smem_set) {
        cudaFuncSetAttribute(moe_gemm_kernel,
                             cudaFuncAttributeMaxDynamicSharedMemorySize, SMEM_BYTES);
        smem_set = 1;
    }
    wsplit_kernel<<<(NE * HID / 4) / 256, 256>>>(w);
    moe_gemm_kernel<<<T / TM, NT, SMEM_BYTES>>>(x, out, T, write_map);
}

// round 16
// speedup vs baseline: 1.2001x; 1.2001x over previous
#include <cuda_runtime.h>
#include <cuda_fp16.h>
#include <math.h>

// MoE router via mma.sync m16n8k16 fp16 2-plane split (3 f32-acc products):
//   logits = x[T,4096] @ W[64,4096]^T; x = xh+xm (exact residual),
//   W*64 = Wh+Wm (exact scale, undone at softmax).
// R16: R12 GEMM verbatim (proven floor: write-ahead inline W split, KSPL=4,
// 3-stage cp.async x, 2 CTAs/SM). top2 reworked: 2 tokens/warp interleaved
// (2x MLP, dual-issue shuffle chains), grid 512.

#define HID  4096
#define NE   64
#define TM   128
#define KC   32
#define KSPL 4
#define KPER (HID / KSPL)         // 1024
#define NCH  (KPER / KC)          // 32
#define NT   256
#define STAGES 3
#define XSTR 40                   // A row stride in floats (160B)
#define XSTGB (TM * XSTR * 4)     // 20480 bytes per x stage
#define WOFF  (STAGES * XSTGB)    // W buffers after the 3 x stages
#define WROWB 160                 // B row stride bytes (20 uint2)
#define WBUFB (NE * WROWB)        // 10240 bytes per W buffer
#define SMEM_BYTES (WOFF + 2 * WBUFB)    // 81920 -> 2 CTAs/SM

static __device__ float g_partial[KSPL * 8192 * NE];   // 8 MB

__device__ __forceinline__ unsigned smem_u32(const void* p) {
    unsigned r;
    asm("{ .reg .u64 t; cvta.to.shared.u64 t, %1; cvt.u32.u64 %0, t; }"
        : "=r"(r) : "l"(p));
    return r;
}
__device__ __forceinline__ void pairsplit(const float* p, unsigned& h, unsigned& m) {
    float2 v = *(const float2*)p;
    __half2 hh = __float22half2_rn(v);
    float2 hb = __half22float2(hh);
    __half2 mm = __float22half2_rn(make_float2(v.x - hb.x, v.y - hb.y));
    h = *(unsigned*)&hh;
    m = *(unsigned*)&mm;
}
__device__ __forceinline__ void valsplit(float2 v, unsigned& h, unsigned& m) {
    __half2 hh = __float22half2_rn(v);
    float2 hb = __half22float2(hh);
    __half2 mm = __float22half2_rn(make_float2(v.x - hb.x, v.y - hb.y));
    h = *(unsigned*)&hh;
    m = *(unsigned*)&mm;
}
__device__ __forceinline__ void mma_f16(float* c, const unsigned* a, const unsigned* b) {
    asm volatile(
        "mma.sync.aligned.m16n8k16.row.col.f32.f16.f16.f32 "
        "{%0,%1,%2,%3},{%4,%5,%6,%7},{%8,%9},{%0,%1,%2,%3};"
        : "+f"(c[0]), "+f"(c[1]), "+f"(c[2]), "+f"(c[3])
        : "r"(a[0]), "r"(a[1]), "r"(a[2]), "r"(a[3]), "r"(b[0]), "r"(b[1]));
}
__device__ __forceinline__ void sts128(unsigned addr, unsigned a, unsigned b,
                                       unsigned cc, unsigned d) {
    asm volatile("st.shared.v4.b32 [%0], {%1,%2,%3,%4};"
                 :: "r"(addr), "r"(a), "r"(b), "r"(cc), "r"(d));
}
#define CP16(dst, src) asm volatile("cp.async.cg.shared.global [%0],[%1],16;" :: "r"(dst), "l"(src))
#define CPCOMMIT()     asm volatile("cp.async.commit_group;")
#define CPWAIT2()      asm volatile("cp.async.wait_group %0;" :: "n"(STAGES - 1))

// -------- kernel 1: split-K(4) GEMM, write-ahead inline W split (R12) ------
__global__ __launch_bounds__(NT, 2) void moe_gemm_kernel(
    const float* __restrict__ x, const float* __restrict__ w, int T)
{
    extern __shared__ char smc[];
    const unsigned sbase = smem_u32(smc);
    const int tid = threadIdx.x;
    const int wid = tid >> 5;
    const int lane = tid & 31;
    const int tok0 = blockIdx.x * TM;
    const int ks = blockIdx.y;
    const int kbase = ks * KPER;

    const float* xsrc[4]; unsigned xdst[4];
    #pragma unroll
    for (int it = 0; it < 4; it++) {
        int u = it * NT + tid, row = u >> 3, c4 = u & 7;
        xsrc[it] = x + (size_t)(tok0 + row) * HID + kbase + c4 * 4;
        xdst[it] = sbase + (unsigned)(row * XSTR + c4 * 4) * 4;
    }
    const float4* wsrc[2]; unsigned wsts[2];
    #pragma unroll
    for (int q = 0; q < 2; q++) {
        int u = q * NT + tid, row = u >> 3, c4 = u & 7;
        wsrc[q] = (const float4*)(w + (size_t)row * HID + kbase + c4 * 4);
        wsts[q] = sbase + WOFF + (unsigned)(row * WROWB + c4 * 16);
    }

    float acc[8][4];
    #pragma unroll
    for (int nt = 0; nt < 8; nt++)
        #pragma unroll
        for (int i = 0; i < 4; i++) acc[nt][i] = 0.f;

    float4 wreg[2];
    #pragma unroll
    for (int q = 0; q < 2; q++) wreg[q] = wsrc[q][0];
    #pragma unroll
    for (int q = 0; q < 2; q++) {
        float4 v = wreg[q];
        unsigned h0, m0, h1, m1;
        valsplit(make_float2(v.x * 64.f, v.y * 64.f), h0, m0);
        valsplit(make_float2(v.z * 64.f, v.w * 64.f), h1, m1);
        sts128(wsts[q], h0, m0, h1, m1);
    }
    #pragma unroll
    for (int q = 0; q < 2; q++) wreg[q] = wsrc[q][KC / 4];
    #pragma unroll
    for (int s = 0; s < 2; s++) {
        unsigned so = (unsigned)(s * XSTGB);
        #pragma unroll
        for (int it = 0; it < 4; it++) CP16(xdst[it] + so, xsrc[it] + s * KC);
        CPCOMMIT();
    }

    const int eq = lane >> 2;
    const int kq = lane & 3;
    const int rbase = wid * 16 + eq;

    #pragma unroll 1
    for (int c = 0; c < NCH; c++) {
        __syncthreads();
        if (c + 2 < NCH) {
            unsigned so = (unsigned)(((c + 2) % STAGES) * XSTGB);
            #pragma unroll
            for (int it = 0; it < 4; it++) CP16(xdst[it] + so, xsrc[it] + (c + 2) * KC);
        }
        if (c + 1 < NCH) {
            unsigned wo = (unsigned)(((c + 1) & 1) * WBUFB);
            #pragma unroll
            for (int q = 0; q < 2; q++) {
                float4 v = wreg[q];
                unsigned h0, m0, h1, m1;
                valsplit(make_float2(v.x * 64.f, v.y * 64.f), h0, m0);
                valsplit(make_float2(v.z * 64.f, v.w * 64.f), h1, m1);
                sts128(wsts[q] + wo, h0, m0, h1, m1);
            }
            if (c + 2 < NCH) {
                #pragma unroll
                for (int q = 0; q < 2; q++) wreg[q] = wsrc[q][(c + 2) * (KC / 4)];
            }
        }
        CPCOMMIT();
        CPWAIT2();
        __syncthreads();

        const float* sx = (const float*)(smc + (c % STAGES) * XSTGB);
        const uint2* bw = (const uint2*)(smc + WOFF + (c & 1) * WBUFB);

        #pragma unroll
        for (int s = 0; s < 2; s++) {
            const int kl = s * 16 + kq * 2;
            unsigned Ah[4], Am[4];
            pairsplit(sx + rbase * XSTR + kl,           Ah[0], Am[0]);
            pairsplit(sx + (rbase + 8) * XSTR + kl,     Ah[1], Am[1]);
            pairsplit(sx + rbase * XSTR + kl + 8,       Ah[2], Am[2]);
            pairsplit(sx + (rbase + 8) * XSTR + kl + 8, Ah[3], Am[3]);
            unsigned Bh[8][2], Bm[8][2];
            #pragma unroll
            for (int nt = 0; nt < 8; nt++) {
                int e = nt * 8 + eq;
                uint2 t0 = bw[e * 20 + s * 8 + kq];
                uint2 t1 = bw[e * 20 + s * 8 + 4 + kq];
                Bh[nt][0] = t0.x; Bm[nt][0] = t0.y;
                Bh[nt][1] = t1.x; Bm[nt][1] = t1.y;
            }
            #pragma unroll
            for (int nt = 0; nt < 8; nt++) {
                mma_f16(acc[nt], Ah, Bh[nt]);
                mma_f16(acc[nt], Ah, Bm[nt]);
                mma_f16(acc[nt], Am, Bh[nt]);
            }
        }
    }

    {
        int row = tok0 + rbase;
        float* d0 = g_partial + ((size_t)ks * T + row) * NE;
        float* d8 = d0 + (size_t)8 * NE;
        #pragma unroll
        for (int nt = 0; nt < 8; nt++) {
            int col = nt * 8 + kq * 2;
            *(float2*)(d0 + col) = make_float2(acc[nt][0], acc[nt][1]);
            *(float2*)(d8 + col) = make_float2(acc[nt][2], acc[nt][3]);
        }
    }
}

// ------ kernel 2: reduce + top-2 + softmax (2 tokens/warp, interleaved) ----
__global__ __launch_bounds__(256) void moe_top2_kernel(float* __restrict__ out,
                                                       int T, int write_map) {
    const int lane = threadIdx.x & 31;
    const int warp = threadIdx.x >> 5;
    const int tb = blockIdx.x * 16 + warp * 2;      // 2 tokens per warp
    const int c0 = lane * 2, c1 = lane * 2 + 1;

    // 8 independent float2 loads in flight
    float2 s[2];
    #pragma unroll
    for (int j = 0; j < 2; j++) {
        float2 a0 = *(const float2*)(g_partial + ((size_t)0 * T + tb + j) * NE + c0);
        float2 a1 = *(const float2*)(g_partial + ((size_t)1 * T + tb + j) * NE + c0);
        float2 a2 = *(const float2*)(g_partial + ((size_t)2 * T + tb + j) * NE + c0);
        float2 a3 = *(const float2*)(g_partial + ((size_t)3 * T + tb + j) * NE + c0);
        s[j] = make_float2((a0.x + a1.x) + (a2.x + a3.x),
                           (a0.y + a1.y) + (a2.y + a3.y));
    }

    float v1[2], v2[2]; int i1[2], i2[2];
    #pragma unroll
    for (int j = 0; j < 2; j++) {
        if (s[j].y > s[j].x) { v1[j] = s[j].y; i1[j] = c1; v2[j] = s[j].x; i2[j] = c0; }
        else                 { v1[j] = s[j].x; i1[j] = c0; v2[j] = s[j].y; i2[j] = c1; }
    }
    // two independent butterfly chains, interleaved for dual issue
    #pragma unroll
    for (int sh = 16; sh >= 1; sh >>= 1) {
        #pragma unroll
        for (int j = 0; j < 2; j++) {
            float ov1 = __shfl_xor_sync(0xffffffffu, v1[j], sh);
            int   oi1 = __shfl_xor_sync(0xffffffffu, i1[j], sh);
            float ov2 = __shfl_xor_sync(0xffffffffu, v2[j], sh);
            int   oi2 = __shfl_xor_sync(0xffffffffu, i2[j], sh);
            bool ob = (ov1 > v1[j]) || (ov1 == v1[j] && oi1 < i1[j]);  // jax tie-break
            float nv1 = ob ? ov1 : v1[j];  int ni1 = ob ? oi1 : i1[j];
            float cv  = ob ? v1[j] : ov1;  int ci  = ob ? i1[j] : oi1;
            float sv  = ob ? ov2 : v2[j];  int si  = ob ? oi2 : i2[j];
            bool b2 = (cv > sv) || (cv == sv && ci < si);
            v2[j] = b2 ? cv : sv; i2[j] = b2 ? ci : si;
            v1[j] = nv1; i1[j] = ni1;
        }
    }
    #pragma unroll
    for (int j = 0; j < 2; j++) {
        // logits carry the exact x64 W scale; undo on the difference (exact)
        float ex = expf((v2[j] - v1[j]) * 0.015625f);   // <= 1, stable
        float inv = 1.f / (1.f + ex);
        float pp1 = inv, pp2 = ex * inv;
        int t = tb + j;
        float2 po;
        po.x = (c0 == i1[j]) ? pp1 : ((c0 == i2[j]) ? pp2 : 0.f);
        po.y = (c1 == i1[j]) ? pp1 : ((c1 == i2[j]) ? pp2 : 0.f);
        *(float2*)(out + (size_t)t * NE + c0) = po;
        if (write_map) {
            float2 mo;
            mo.x = (c0 == i1[j] || c0 == i2[j]) ? 1.f : 0.f;
            mo.y = (c1 == i1[j] || c1 == i2[j]) ? 1.f : 0.f;
            *(float2*)(out + (size_t)T * NE + (size_t)t * NE + c0) = mo;
        }
    }
}

extern "C" void kernel_launch(void* const* d_in, const int* in_sizes, int n_in,
                              void* d_out, int out_size) {
    const float* x = (const float*)d_in[0];   // [2048,4,4096] fp32
    const float* w = (const float*)d_in[1];   // [64,4096] fp32
    float* out = (float*)d_out;
    int T = in_sizes[0] / HID;                // 8192
    int write_map = (out_size >= 2 * T * NE) ? 1 : 0;

    static int smem_set = 0;
    if (!smem_set) {
        cudaFuncSetAttribute(moe_gemm_kernel,
                             cudaFuncAttributeMaxDynamicSharedMemorySize, SMEM_BYTES);
        smem_set = 1;
    }
    dim3 grid(T / TM, KSPL);
    moe_gemm_kernel<<<grid, NT, SMEM_BYTES>>>(x, w, T);
    moe_top2_kernel<<<T / 16, 256>>>(out, T, write_map);
}